// round 9
// baseline (speedup 1.0000x reference)
#include <cuda_runtime.h>
#include <cuda_bf16.h>
#include <math.h>
#include <stdint.h>

#define BB 64
#define TT 20
#define EE 512
#define VV 32000
#define G4 2048   // 4*EE
#define NSTEP (TT - 1)

// ---------------- scratch (no allocations allowed) ----------------
__device__ float g_h[BB * EE];
__device__ float g_c[BB * EE];
__device__ float g_xgates[NSTEP * BB * G4];      // [(t-1)*64+b][4E]
__device__ unsigned g_bars[64];                  // grid-barrier slots (zeroed per call)
__device__ __nv_bfloat16 g_Ehi[TT * BB * EE];    // emb split [t*64+b][e]
__device__ __nv_bfloat16 g_Elo[TT * BB * EE];
__device__ __nv_bfloat16 g_Shi[BB * TT * EE];    // seq split [b*20+t][e] (proj A operand)
__device__ __nv_bfloat16 g_Slo[BB * TT * EE];
__device__ __nv_bfloat16 g_WoutHi[(size_t)VV * EE];
__device__ __nv_bfloat16 g_WoutLo[(size_t)VV * EE];
__device__ __nv_bfloat16 g_WihHi[G4 * EE];
__device__ __nv_bfloat16 g_WihLo[G4 * EE];

// ================= helpers =================
__device__ __forceinline__ uint32_t smem_u32(const void* p) {
    uint32_t a;
    asm("{ .reg .u64 t; cvta.to.shared.u64 t, %1; cvt.u32.u64 %0, t; }" : "=r"(a) : "l"(p));
    return a;
}
__device__ __forceinline__ void bf16_split(float v, __nv_bfloat16& h, __nv_bfloat16& l) {
    h = __float2bfloat16(v);
    l = __float2bfloat16(v - __bfloat162float(h));
}

#define LDSM4(r, a)                                                            \
    asm volatile("ldmatrix.sync.aligned.m8n8.x4.shared.b16 {%0,%1,%2,%3}, [%4];" \
        : "=r"((r)[0]), "=r"((r)[1]), "=r"((r)[2]), "=r"((r)[3]) : "r"(a))
#define LDSM2(r, a)                                                            \
    asm volatile("ldmatrix.sync.aligned.m8n8.x2.shared.b16 {%0,%1}, [%2];"     \
        : "=r"((r)[0]), "=r"((r)[1]) : "r"(a))
#define MMA_BF16(acc, a, b)                                                    \
    asm volatile("mma.sync.aligned.m16n8k16.row.col.f32.bf16.bf16.f32 "        \
        "{%0,%1,%2,%3}, {%4,%5,%6,%7}, {%8,%9}, {%0,%1,%2,%3};"                \
        : "+f"((acc)[0]), "+f"((acc)[1]), "+f"((acc)[2]), "+f"((acc)[3])       \
        : "r"((a)[0]), "r"((a)[1]), "r"((a)[2]), "r"((a)[3]),                  \
          "r"((b)[0]), "r"((b)[1]))
#define CP_ASYNC16(sp, gp)                                                     \
    asm volatile("cp.async.cg.shared.global [%0], [%1], 16;" :: "r"(sp), "l"(gp))

// ================= HMMA bf16-split GEMM (512 threads, 16 warps) =================
// C[m0:128, n0:128] = Ahi*Bhi + Ahi*Blo + Alo*Bhi  (A [*,512] row-major, B [N,512] row-major)
// K = 512 fixed. bias1 (+bias2) added. Store guarded by m < mrows.
// Warp grid 4M x 4N, warp tile 32x32 -> 4 warps per SMSP for latency hiding.
#define BK 32
#define SR 80                  // smem row stride bytes (64B data + 16B pad)
#define OPB (128 * SR)         // bytes per operand tile (10240)
#define BUFB (4 * OPB)         // per buffer (40960)
#define SMEMB (2 * BUFB)       // 81920

__global__ __launch_bounds__(512, 1) void hmma_gemm_kernel(
        const __nv_bfloat16* __restrict__ Ahi, const __nv_bfloat16* __restrict__ Alo,
        const __nv_bfloat16* __restrict__ Bhi, const __nv_bfloat16* __restrict__ Blo,
        float* __restrict__ C, int ldc,
        const float* __restrict__ bias1, const float* __restrict__ bias2, int mrows) {
    extern __shared__ char smem[];
    uint32_t sb = smem_u32(smem);
    int tid = threadIdx.x, lane = tid & 31, wid = tid >> 5;
    int wm = (wid & 3) * 32;        // warp M offset in tile
    int wn = (wid >> 2) * 32;       // warp N offset in tile
    int m0 = blockIdx.x * 128;
    int n0 = blockIdx.y * 128;

    float acc[2][4][4];
#pragma unroll
    for (int i = 0; i < 2; i++)
#pragma unroll
        for (int j = 0; j < 4; j++)
#pragma unroll
            for (int k = 0; k < 4; k++) acc[i][j][k] = 0.f;

    // ---- async tile loader: 2048 16B units (4 operands x 128 rows x 4 units) ----
#define LOAD_CHUNK(kc, buf)                                                          \
    do {                                                                             \
        _Pragma("unroll")                                                            \
        for (int i_ = 0; i_ < 4; i_++) {                                             \
            int u_ = tid + i_ * 512;                                                 \
            int tl_ = u_ >> 9;                                                       \
            int q_ = u_ & 511;                                                       \
            int r_ = q_ >> 2;                                                        \
            int c_ = q_ & 3;                                                         \
            const __nv_bfloat16* src_ = (tl_ == 0) ? Ahi : (tl_ == 1) ? Alo          \
                                       : (tl_ == 2) ? Bhi : Blo;                     \
            int grow_ = ((tl_ < 2) ? m0 : n0) + r_;                                  \
            const void* gp_ = src_ + (size_t)grow_ * EE + (kc) * BK + c_ * 8;        \
            uint32_t sp_ = sb + (buf) * BUFB + tl_ * OPB + r_ * SR + c_ * 16;        \
            CP_ASYNC16(sp_, gp_);                                                    \
        }                                                                            \
        asm volatile("cp.async.commit_group;");                                      \
    } while (0)

    LOAD_CHUNK(0, 0);

    for (int kc = 0; kc < 16; kc++) {
        int buf = kc & 1;
        if (kc < 15) {
            LOAD_CHUNK(kc + 1, buf ^ 1);
            asm volatile("cp.async.wait_group 1;");
        } else {
            asm volatile("cp.async.wait_group 0;");
        }
        __syncthreads();

        uint32_t base = sb + buf * BUFB;
#pragma unroll
        for (int ks = 0; ks < 2; ks++) {
            int kk = ks * 32;   // byte offset of k16 step (16 bf16 = 32B)
            uint32_t ah[2][4], al[2][4];
#pragma unroll
            for (int mi = 0; mi < 2; mi++) {
                uint32_t ra = base + (uint32_t)(wm + mi * 16 + (lane & 15)) * SR
                            + kk + ((lane >> 4) << 4);
                LDSM4(ah[mi], ra);
                LDSM4(al[mi], ra + OPB);
            }
#pragma unroll
            for (int ni = 0; ni < 4; ni++) {
                uint32_t rb = base + 2 * OPB
                            + (uint32_t)(wn + ni * 8 + (lane & 7)) * SR
                            + kk + (((lane >> 3) & 1) << 4);
                uint32_t bh[2], bl[2];
                LDSM2(bh, rb);
                LDSM2(bl, rb + OPB);
#pragma unroll
                for (int mi = 0; mi < 2; mi++) {
                    MMA_BF16(acc[mi][ni], ah[mi], bh);
                    MMA_BF16(acc[mi][ni], ah[mi], bl);
                    MMA_BF16(acc[mi][ni], al[mi], bh);
                }
            }
        }
        __syncthreads();
    }

    // ---- epilogue ----
#pragma unroll
    for (int ni = 0; ni < 4; ni++) {
        int c0 = n0 + wn + ni * 8 + (lane & 3) * 2;
        float b0 = bias1[c0], b1 = bias1[c0 + 1];
        if (bias2) { b0 += bias2[c0]; b1 += bias2[c0 + 1]; }
#pragma unroll
        for (int mi = 0; mi < 2; mi++) {
            int r0 = m0 + wm + mi * 16 + (lane >> 2);
            float* p = C + (size_t)r0 * ldc + c0;
            if (r0 < mrows) {
                float2 v = make_float2(acc[mi][ni][0] + b0, acc[mi][ni][1] + b1);
                *(float2*)p = v;
            }
            if (r0 + 8 < mrows) {
                float2 v = make_float2(acc[mi][ni][2] + b0, acc[mi][ni][3] + b1);
                *(float2*)(p + (size_t)8 * ldc) = v;
            }
        }
    }
}

// ================= fp32 -> (bf16 hi, bf16 lo) split =================
__global__ void split_kernel(const float* __restrict__ src,
                             __nv_bfloat16* __restrict__ hi,
                             __nv_bfloat16* __restrict__ lo, int n4) {
    int i = blockIdx.x * blockDim.x + threadIdx.x;
    if (i >= n4) return;
    float4 v = ((const float4*)src)[i];
    __nv_bfloat16 h0, h1, h2, h3, l0, l1, l2, l3;
    bf16_split(v.x, h0, l0); bf16_split(v.y, h1, l1);
    bf16_split(v.z, h2, l2); bf16_split(v.w, h3, l3);
    ((__nv_bfloat162*)hi)[2 * i + 0] = __halves2bfloat162(h0, h1);
    ((__nv_bfloat162*)hi)[2 * i + 1] = __halves2bfloat162(h2, h3);
    ((__nv_bfloat162*)lo)[2 * i + 0] = __halves2bfloat162(l0, l1);
    ((__nv_bfloat162*)lo)[2 * i + 1] = __halves2bfloat162(l2, l3);
}

// ================= embedding gather: split emb; seq row 0 =================
__global__ void gather_kernel(const int* __restrict__ captions,
                              const float* __restrict__ W_emb) {
    int idx = blockIdx.x * blockDim.x + threadIdx.x;
    if (idx >= TT * BB * EE) return;
    int e = idx % EE;
    int b = (idx / EE) % BB;
    int t = idx / (EE * BB);
    float v = W_emb[(size_t)captions[b * TT + t] * EE + e];
    __nv_bfloat16 h, l;
    bf16_split(v, h, l);
    g_Ehi[idx] = h;
    g_Elo[idx] = l;
    if (t == 0) {                               // seq[:,0] = emb[:,0]
        size_t s = ((size_t)b * TT) * EE + e;
        g_Shi[s] = h;
        g_Slo[s] = l;
    }
}

// ================= h=0, c=features, barrier slots = 0 =================
__global__ void init_state_kernel(const float* __restrict__ features) {
    int idx = blockIdx.x * blockDim.x + threadIdx.x;
    if (idx < BB * EE) { g_h[idx] = 0.f; g_c[idx] = features[idx]; }
    if (idx < 64) g_bars[idx] = 0u;
}

// ================= persistent LSTM: all 19 steps in one kernel =================
__device__ __forceinline__ void gridbar(int slot) {
    __syncthreads();
    __threadfence();
    if (threadIdx.x == 0) {
        atomicAdd(&g_bars[slot], 1u);
        while (*(volatile unsigned*)&g_bars[slot] < 128u) {}
    }
    __syncthreads();
    __threadfence();
}

__global__ __launch_bounds__(256) void lstm_persist_kernel(const float* __restrict__ W_hh) {
    __shared__ float Xs[64][36];
    __shared__ float Ws[64][36];
    int blk = blockIdx.x;
    int tid = threadIdx.x;
    int n0 = (blk & 31) * 64;
    int koff = (blk >> 5) * 128;
    int tx = tid & 15, ty = tid >> 4;

    for (int t = 1; t < TT; t++) {
        if (t > 1) {
            // ---- phase A: gates[(t-1)] += h @ W_hh^T (64x64 x K128 slice) ----
            float acc[4][4] = {};
            for (int kc = 0; kc < 128; kc += 32) {
#pragma unroll
                for (int i = 0; i < 2; i++) {
                    int q = tid + i * 256;
                    int r = q >> 3;
                    int kk = (q & 7) << 2;
                    *(float4*)(&Xs[r][kk]) =
                        *(const float4*)(g_h + (size_t)r * EE + koff + kc + kk);
                    *(float4*)(&Ws[r][kk]) =
                        *(const float4*)(W_hh + (size_t)(n0 + r) * EE + koff + kc + kk);
                }
                __syncthreads();
#pragma unroll
                for (int k4 = 0; k4 < 8; k4++) {
                    float4 xr[4], wr[4];
#pragma unroll
                    for (int i = 0; i < 4; i++) xr[i] = *(const float4*)(&Xs[ty * 4 + i][k4 * 4]);
#pragma unroll
                    for (int j = 0; j < 4; j++) wr[j] = *(const float4*)(&Ws[tx * 4 + j][k4 * 4]);
#pragma unroll
                    for (int i = 0; i < 4; i++)
#pragma unroll
                        for (int j = 0; j < 4; j++)
                            acc[i][j] += xr[i].x * wr[j].x + xr[i].y * wr[j].y
                                       + xr[i].z * wr[j].z + xr[i].w * wr[j].w;
                }
                __syncthreads();
            }
#pragma unroll
            for (int i = 0; i < 4; i++)
#pragma unroll
                for (int j = 0; j < 4; j++)
                    atomicAdd(&g_xgates[((size_t)(t - 1) * BB + ty * 4 + i) * G4
                                        + n0 + tx * 4 + j],
                              acc[i][j]);

            gridbar(2 * (t - 1));
        }

        // ---- phase B: pointwise (one element per thread) ----
        {
            int idx = blk * 256 + tid;          // 0..32767
            int bb = idx >> 9, n = idx & 511;
            const float* gp = g_xgates + ((size_t)(t - 1) * BB + bb) * G4 + n;
            float gi = gp[0];
            float gf = gp[EE];
            float gg = gp[2 * EE];
            float go = gp[3 * EE];
            float iv = 1.f / (1.f + expf(-gi));
            float fv = 1.f / (1.f + expf(-gf));
            float gv = tanhf(gg);
            float ov = 1.f / (1.f + expf(-go));
            float c = fv * g_c[idx] + iv * gv;
            g_c[idx] = c;
            float h = ov * tanhf(c);
            g_h[idx] = h;
            __nv_bfloat16 hh, hl;
            bf16_split(h, hh, hl);
            size_t s = ((size_t)bb * TT + t) * EE + n;
            g_Shi[s] = hh;
            g_Slo[s] = hl;
        }

        if (t < TT - 1) gridbar(2 * (t - 1) + 1);
    }
}

// ================= launch =================
extern "C" void kernel_launch(void* const* d_in, const int* in_sizes, int n_in,
                              void* d_out, int out_size) {
    const float* features = (const float*)d_in[0];
    const int*   captions = (const int*)d_in[1];
    const float* W_emb    = (const float*)d_in[2];
    const float* W_out    = (const float*)d_in[3];
    const float* b_out    = (const float*)d_in[4];
    const float* W_ih     = (const float*)d_in[5];
    const float* W_hh     = (const float*)d_in[6];
    const float* b_ih     = (const float*)d_in[7];
    const float* b_hh     = (const float*)d_in[8];
    float* out = (float*)d_out;

    cudaFuncSetAttribute(hmma_gemm_kernel, cudaFuncAttributeMaxDynamicSharedMemorySize, SMEMB);

    void *pEhi, *pElo, *pShi, *pSlo, *pWoH, *pWoL, *pWiH, *pWiL, *pXg;
    cudaGetSymbolAddress(&pEhi, g_Ehi);
    cudaGetSymbolAddress(&pElo, g_Elo);
    cudaGetSymbolAddress(&pShi, g_Shi);
    cudaGetSymbolAddress(&pSlo, g_Slo);
    cudaGetSymbolAddress(&pWoH, g_WoutHi);
    cudaGetSymbolAddress(&pWoL, g_WoutLo);
    cudaGetSymbolAddress(&pWiH, g_WihHi);
    cudaGetSymbolAddress(&pWiL, g_WihLo);
    cudaGetSymbolAddress(&pXg, g_xgates);

    gather_kernel<<<(TT * BB * EE + 255) / 256, 256>>>(captions, W_emb);
    init_state_kernel<<<(BB * EE + 255) / 256, 256>>>(features);

    // x-part of all LSTM steps: xgates = emb @ W_ih^T + b_ih + b_hh  (tensor cores)
    split_kernel<<<(G4 * EE / 4 + 255) / 256, 256>>>(W_ih,
        (__nv_bfloat16*)pWiH, (__nv_bfloat16*)pWiL, G4 * EE / 4);
    hmma_gemm_kernel<<<dim3((NSTEP * BB + 127) / 128, G4 / 128), 512, SMEMB>>>(
        (const __nv_bfloat16*)pEhi, (const __nv_bfloat16*)pElo,
        (const __nv_bfloat16*)pWiH, (const __nv_bfloat16*)pWiL,
        (float*)pXg, G4, b_ih, b_hh, NSTEP * BB);

    // W_out split (independent; cheap)
    split_kernel<<<((int)((size_t)VV * EE / 4) + 255) / 256, 256>>>(W_out,
        (__nv_bfloat16*)pWoH, (__nv_bfloat16*)pWoL, (int)((size_t)VV * EE / 4));

    // serial LSTM (recurrent half), one persistent kernel
    lstm_persist_kernel<<<128, 256>>>(W_hh);

    // projection: out = seq @ W_out^T + b_out  (tensor cores)
    hmma_gemm_kernel<<<dim3((TT * BB) / 128, VV / 128), 512, SMEMB>>>(
        (const __nv_bfloat16*)pShi, (const __nv_bfloat16*)pSlo,
        (const __nv_bfloat16*)pWoH, (const __nv_bfloat16*)pWoL,
        out, VV, b_out, nullptr, TT * BB);
}

// round 10
// speedup vs baseline: 1.0698x; 1.0698x over previous
#include <cuda_runtime.h>
#include <cuda_bf16.h>
#include <math.h>
#include <stdint.h>

#define BB 64
#define TT 20
#define EE 512
#define VV 32000
#define G4 2048   // 4*EE
#define NSTEP (TT - 1)

// ---------------- scratch (no allocations allowed) ----------------
__device__ float g_h[BB * EE];
__device__ float g_c[BB * EE];
__device__ float g_xgates[NSTEP * BB * G4];      // [(t-1)*64+b][4E]
__device__ unsigned g_bars[64];                  // grid-barrier slots (zeroed per call)
__device__ __nv_bfloat16 g_Ehi[TT * BB * EE];    // emb split [t*64+b][e]
__device__ __nv_bfloat16 g_Elo[TT * BB * EE];
__device__ __nv_bfloat16 g_Shi[BB * TT * EE];    // seq split [b*20+t][e] (proj A operand)
__device__ __nv_bfloat16 g_Slo[BB * TT * EE];
__device__ __nv_bfloat16 g_WoutHi[(size_t)VV * EE];
__device__ __nv_bfloat16 g_WoutLo[(size_t)VV * EE];
__device__ __nv_bfloat16 g_WihHi[G4 * EE];
__device__ __nv_bfloat16 g_WihLo[G4 * EE];

// ================= helpers =================
__device__ __forceinline__ uint32_t smem_u32(const void* p) {
    uint32_t a;
    asm("{ .reg .u64 t; cvta.to.shared.u64 t, %1; cvt.u32.u64 %0, t; }" : "=r"(a) : "l"(p));
    return a;
}
__device__ __forceinline__ void bf16_split(float v, __nv_bfloat16& h, __nv_bfloat16& l) {
    h = __float2bfloat16(v);
    l = __float2bfloat16(v - __bfloat162float(h));
}

#define LDSM4(r, a)                                                            \
    asm volatile("ldmatrix.sync.aligned.m8n8.x4.shared.b16 {%0,%1,%2,%3}, [%4];" \
        : "=r"((r)[0]), "=r"((r)[1]), "=r"((r)[2]), "=r"((r)[3]) : "r"(a))
#define LDSM2(r, a)                                                            \
    asm volatile("ldmatrix.sync.aligned.m8n8.x2.shared.b16 {%0,%1}, [%2];"     \
        : "=r"((r)[0]), "=r"((r)[1]) : "r"(a))
#define MMA_BF16(acc, a, b)                                                    \
    asm volatile("mma.sync.aligned.m16n8k16.row.col.f32.bf16.bf16.f32 "        \
        "{%0,%1,%2,%3}, {%4,%5,%6,%7}, {%8,%9}, {%0,%1,%2,%3};"                \
        : "+f"((acc)[0]), "+f"((acc)[1]), "+f"((acc)[2]), "+f"((acc)[3])       \
        : "r"((a)[0]), "r"((a)[1]), "r"((a)[2]), "r"((a)[3]),                  \
          "r"((b)[0]), "r"((b)[1]))
#define CP_ASYNC16(sp, gp)                                                     \
    asm volatile("cp.async.cg.shared.global [%0], [%1], 16;" :: "r"(sp), "l"(gp))

// ================= HMMA bf16-split GEMM =================
// CTA tile 128(M) x 256(N), 8 warps in 2x4 grid, warp tile 64x64.
// C = Ahi*Bhi + Ahi*Blo + Alo*Bhi ; A [*,512] row-major, B [N,512] row-major.
// K = 512 fixed. bias1 (+bias2) added. Stores guarded by m < mrows.
#define BK 32
#define SRW 80                   // smem row stride bytes (64B data + 16B pad)
#define A_OP (128 * SRW)         // 10240 B per A operand tile
#define B_OP (256 * SRW)         // 20480 B per B operand tile
#define STAGEB (2 * A_OP + 2 * B_OP)  // 61440
#define SMEMB (2 * STAGEB)            // 122880

__global__ __launch_bounds__(256, 1) void hmma_gemm_kernel(
        const __nv_bfloat16* __restrict__ Ahi, const __nv_bfloat16* __restrict__ Alo,
        const __nv_bfloat16* __restrict__ Bhi, const __nv_bfloat16* __restrict__ Blo,
        float* __restrict__ C, int ldc,
        const float* __restrict__ bias1, const float* __restrict__ bias2, int mrows) {
    extern __shared__ char smem[];
    uint32_t sb = smem_u32(smem);
    int tid = threadIdx.x, lane = tid & 31, wid = tid >> 5;
    int wm = (wid & 1) * 64;        // warp M offset in tile
    int wn = (wid >> 1) * 64;       // warp N offset in tile
    int m0 = blockIdx.x * 128;
    int n0 = blockIdx.y * 256;

    float acc[4][8][4];
#pragma unroll
    for (int i = 0; i < 4; i++)
#pragma unroll
        for (int j = 0; j < 8; j++)
#pragma unroll
            for (int k = 0; k < 4; k++) acc[i][j][k] = 0.f;

    // ---- async stage loader: 3072 16B units (A hi/lo 1024 + B hi/lo 2048) ----
#define LOAD_CHUNK(kc, buf)                                                          \
    do {                                                                             \
        _Pragma("unroll")                                                            \
        for (int i_ = 0; i_ < 12; i_++) {                                            \
            int u_ = tid + i_ * 256;                                                 \
            const __nv_bfloat16* src_;                                               \
            uint32_t sp_;                                                            \
            int grow_, c_;                                                           \
            if (u_ < 1024) {                  /* A tiles */                           \
                int op_ = u_ >> 9;                                                   \
                int q_ = u_ & 511;                                                   \
                int r_ = q_ >> 2;                                                    \
                c_ = q_ & 3;                                                         \
                src_ = op_ ? Alo : Ahi;                                              \
                grow_ = m0 + r_;                                                     \
                sp_ = sb + (buf) * STAGEB + op_ * A_OP + r_ * SRW + c_ * 16;         \
            } else {                          /* B tiles */                          \
                int v_ = u_ - 1024;                                                  \
                int op_ = v_ >> 10;                                                  \
                int q_ = v_ & 1023;                                                  \
                int r_ = q_ >> 2;                                                    \
                c_ = q_ & 3;                                                         \
                src_ = op_ ? Blo : Bhi;                                              \
                grow_ = n0 + r_;                                                     \
                sp_ = sb + (buf) * STAGEB + 2 * A_OP + op_ * B_OP + r_ * SRW + c_ * 16; \
            }                                                                        \
            const void* gp_ = src_ + (size_t)grow_ * EE + (kc) * BK + c_ * 8;        \
            CP_ASYNC16(sp_, gp_);                                                    \
        }                                                                            \
        asm volatile("cp.async.commit_group;");                                      \
    } while (0)

    LOAD_CHUNK(0, 0);

    for (int kc = 0; kc < 16; kc++) {
        int buf = kc & 1;
        if (kc < 15) {
            LOAD_CHUNK(kc + 1, buf ^ 1);
            asm volatile("cp.async.wait_group 1;");
        } else {
            asm volatile("cp.async.wait_group 0;");
        }
        __syncthreads();

        uint32_t base = sb + buf * STAGEB;
#pragma unroll
        for (int ks = 0; ks < 2; ks++) {
            int kk = ks * 32;   // byte offset of k16 step (16 bf16 = 32B)
            uint32_t ah[4][4], al[4][4];
#pragma unroll
            for (int mi = 0; mi < 4; mi++) {
                uint32_t ra = base + (uint32_t)(wm + mi * 16 + (lane & 15)) * SRW
                            + kk + ((lane >> 4) << 4);
                LDSM4(ah[mi], ra);
                LDSM4(al[mi], ra + A_OP);
            }
#pragma unroll
            for (int ni = 0; ni < 8; ni++) {
                uint32_t rb = base + 2 * A_OP
                            + (uint32_t)(wn + ni * 8 + (lane & 7)) * SRW
                            + kk + (((lane >> 3) & 1) << 4);
                uint32_t bh[2], bl[2];
                LDSM2(bh, rb);
                LDSM2(bl, rb + B_OP);
#pragma unroll
                for (int mi = 0; mi < 4; mi++) {
                    MMA_BF16(acc[mi][ni], ah[mi], bh);
                    MMA_BF16(acc[mi][ni], ah[mi], bl);
                    MMA_BF16(acc[mi][ni], al[mi], bh);
                }
            }
        }
        __syncthreads();
    }

    // ---- epilogue ----
#pragma unroll
    for (int ni = 0; ni < 8; ni++) {
        int c0 = n0 + wn + ni * 8 + (lane & 3) * 2;
        float b0 = bias1[c0], b1 = bias1[c0 + 1];
        if (bias2) { b0 += bias2[c0]; b1 += bias2[c0 + 1]; }
#pragma unroll
        for (int mi = 0; mi < 4; mi++) {
            int r0 = m0 + wm + mi * 16 + (lane >> 2);
            float* p = C + (size_t)r0 * ldc + c0;
            if (r0 < mrows) {
                float2 v = make_float2(acc[mi][ni][0] + b0, acc[mi][ni][1] + b1);
                *(float2*)p = v;
            }
            if (r0 + 8 < mrows) {
                float2 v = make_float2(acc[mi][ni][2] + b0, acc[mi][ni][3] + b1);
                *(float2*)(p + (size_t)8 * ldc) = v;
            }
        }
    }
}

// ================= fp32 -> (bf16 hi, bf16 lo) split =================
__global__ void split_kernel(const float* __restrict__ src,
                             __nv_bfloat16* __restrict__ hi,
                             __nv_bfloat16* __restrict__ lo, int n4) {
    int i = blockIdx.x * blockDim.x + threadIdx.x;
    if (i >= n4) return;
    float4 v = ((const float4*)src)[i];
    __nv_bfloat16 h0, h1, h2, h3, l0, l1, l2, l3;
    bf16_split(v.x, h0, l0); bf16_split(v.y, h1, l1);
    bf16_split(v.z, h2, l2); bf16_split(v.w, h3, l3);
    ((__nv_bfloat162*)hi)[2 * i + 0] = __halves2bfloat162(h0, h1);
    ((__nv_bfloat162*)hi)[2 * i + 1] = __halves2bfloat162(h2, h3);
    ((__nv_bfloat162*)lo)[2 * i + 0] = __halves2bfloat162(l0, l1);
    ((__nv_bfloat162*)lo)[2 * i + 1] = __halves2bfloat162(l2, l3);
}

// ================= embedding gather: split emb; seq row 0 =================
__global__ void gather_kernel(const int* __restrict__ captions,
                              const float* __restrict__ W_emb) {
    int idx = blockIdx.x * blockDim.x + threadIdx.x;
    if (idx >= TT * BB * EE) return;
    int e = idx % EE;
    int b = (idx / EE) % BB;
    int t = idx / (EE * BB);
    float v = W_emb[(size_t)captions[b * TT + t] * EE + e];
    __nv_bfloat16 h, l;
    bf16_split(v, h, l);
    g_Ehi[idx] = h;
    g_Elo[idx] = l;
    if (t == 0) {                               // seq[:,0] = emb[:,0]
        size_t s = ((size_t)b * TT) * EE + e;
        g_Shi[s] = h;
        g_Slo[s] = l;
    }
}

// ================= h=0, c=features, barrier slots = 0 =================
__global__ void init_state_kernel(const float* __restrict__ features) {
    int idx = blockIdx.x * blockDim.x + threadIdx.x;
    if (idx < BB * EE) { g_h[idx] = 0.f; g_c[idx] = features[idx]; }
    if (idx < 64) g_bars[idx] = 0u;
}

// ================= persistent LSTM: all 19 steps in one kernel =================
__device__ __forceinline__ void gridbar(int slot) {
    __syncthreads();
    __threadfence();
    if (threadIdx.x == 0) {
        atomicAdd(&g_bars[slot], 1u);
        while (*(volatile unsigned*)&g_bars[slot] < 128u) {}
    }
    __syncthreads();
    __threadfence();
}

__global__ __launch_bounds__(256) void lstm_persist_kernel(const float* __restrict__ W_hh) {
    __shared__ float Xs[64][36];
    __shared__ float Ws[64][36];
    int blk = blockIdx.x;
    int tid = threadIdx.x;
    int n0 = (blk & 31) * 64;
    int koff = (blk >> 5) * 128;
    int tx = tid & 15, ty = tid >> 4;

    for (int t = 1; t < TT; t++) {
        if (t > 1) {
            // ---- phase A: gates[(t-1)] += h @ W_hh^T (64x64 x K128 slice) ----
            float acc[4][4] = {};
            for (int kc = 0; kc < 128; kc += 32) {
#pragma unroll
                for (int i = 0; i < 2; i++) {
                    int q = tid + i * 256;
                    int r = q >> 3;
                    int kk = (q & 7) << 2;
                    *(float4*)(&Xs[r][kk]) =
                        *(const float4*)(g_h + (size_t)r * EE + koff + kc + kk);
                    *(float4*)(&Ws[r][kk]) =
                        *(const float4*)(W_hh + (size_t)(n0 + r) * EE + koff + kc + kk);
                }
                __syncthreads();
#pragma unroll
                for (int k4 = 0; k4 < 8; k4++) {
                    float4 xr[4], wr[4];
#pragma unroll
                    for (int i = 0; i < 4; i++) xr[i] = *(const float4*)(&Xs[ty * 4 + i][k4 * 4]);
#pragma unroll
                    for (int j = 0; j < 4; j++) wr[j] = *(const float4*)(&Ws[tx * 4 + j][k4 * 4]);
#pragma unroll
                    for (int i = 0; i < 4; i++)
#pragma unroll
                        for (int j = 0; j < 4; j++)
                            acc[i][j] += xr[i].x * wr[j].x + xr[i].y * wr[j].y
                                       + xr[i].z * wr[j].z + xr[i].w * wr[j].w;
                }
                __syncthreads();
            }
#pragma unroll
            for (int i = 0; i < 4; i++)
#pragma unroll
                for (int j = 0; j < 4; j++)
                    atomicAdd(&g_xgates[((size_t)(t - 1) * BB + ty * 4 + i) * G4
                                        + n0 + tx * 4 + j],
                              acc[i][j]);

            gridbar(2 * (t - 1));
        }

        // ---- phase B: pointwise (one element per thread) ----
        {
            int idx = blk * 256 + tid;          // 0..32767
            int bb = idx >> 9, n = idx & 511;
            const float* gp = g_xgates + ((size_t)(t - 1) * BB + bb) * G4 + n;
            float gi = gp[0];
            float gf = gp[EE];
            float gg = gp[2 * EE];
            float go = gp[3 * EE];
            float iv = 1.f / (1.f + expf(-gi));
            float fv = 1.f / (1.f + expf(-gf));
            float gv = tanhf(gg);
            float ov = 1.f / (1.f + expf(-go));
            float c = fv * g_c[idx] + iv * gv;
            g_c[idx] = c;
            float h = ov * tanhf(c);
            g_h[idx] = h;
            __nv_bfloat16 hh, hl;
            bf16_split(h, hh, hl);
            size_t s = ((size_t)bb * TT + t) * EE + n;
            g_Shi[s] = hh;
            g_Slo[s] = hl;
        }

        if (t < TT - 1) gridbar(2 * (t - 1) + 1);
    }
}

// ================= launch =================
extern "C" void kernel_launch(void* const* d_in, const int* in_sizes, int n_in,
                              void* d_out, int out_size) {
    const float* features = (const float*)d_in[0];
    const int*   captions = (const int*)d_in[1];
    const float* W_emb    = (const float*)d_in[2];
    const float* W_out    = (const float*)d_in[3];
    const float* b_out    = (const float*)d_in[4];
    const float* W_ih     = (const float*)d_in[5];
    const float* W_hh     = (const float*)d_in[6];
    const float* b_ih     = (const float*)d_in[7];
    const float* b_hh     = (const float*)d_in[8];
    float* out = (float*)d_out;

    cudaFuncSetAttribute(hmma_gemm_kernel, cudaFuncAttributeMaxDynamicSharedMemorySize, SMEMB);

    void *pEhi, *pElo, *pShi, *pSlo, *pWoH, *pWoL, *pWiH, *pWiL, *pXg;
    cudaGetSymbolAddress(&pEhi, g_Ehi);
    cudaGetSymbolAddress(&pElo, g_Elo);
    cudaGetSymbolAddress(&pShi, g_Shi);
    cudaGetSymbolAddress(&pSlo, g_Slo);
    cudaGetSymbolAddress(&pWoH, g_WoutHi);
    cudaGetSymbolAddress(&pWoL, g_WoutLo);
    cudaGetSymbolAddress(&pWiH, g_WihHi);
    cudaGetSymbolAddress(&pWiL, g_WihLo);
    cudaGetSymbolAddress(&pXg, g_xgates);

    gather_kernel<<<(TT * BB * EE + 255) / 256, 256>>>(captions, W_emb);
    init_state_kernel<<<(BB * EE + 255) / 256, 256>>>(features);

    // x-part of all LSTM steps: xgates = emb @ W_ih^T + b_ih + b_hh  (tensor cores)
    split_kernel<<<(G4 * EE / 4 + 255) / 256, 256>>>(W_ih,
        (__nv_bfloat16*)pWiH, (__nv_bfloat16*)pWiL, G4 * EE / 4);
    hmma_gemm_kernel<<<dim3((NSTEP * BB + 127) / 128, G4 / 256), 256, SMEMB>>>(
        (const __nv_bfloat16*)pEhi, (const __nv_bfloat16*)pElo,
        (const __nv_bfloat16*)pWiH, (const __nv_bfloat16*)pWiL,
        (float*)pXg, G4, b_ih, b_hh, NSTEP * BB);

    // W_out split (independent; cheap)
    split_kernel<<<((int)((size_t)VV * EE / 4) + 255) / 256, 256>>>(W_out,
        (__nv_bfloat16*)pWoH, (__nv_bfloat16*)pWoL, (int)((size_t)VV * EE / 4));

    // serial LSTM (recurrent half), one persistent kernel
    lstm_persist_kernel<<<128, 256>>>(W_hh);

    // projection: out = seq @ W_out^T + b_out  (tensor cores)
    hmma_gemm_kernel<<<dim3((TT * BB) / 128, VV / 256), 256, SMEMB>>>(
        (const __nv_bfloat16*)pShi, (const __nv_bfloat16*)pSlo,
        (const __nv_bfloat16*)pWoH, (const __nv_bfloat16*)pWoL,
        out, VV, b_out, nullptr, TT * BB);
}